// round 15
// baseline (speedup 1.0000x reference)
#include <cuda_runtime.h>
#include <cuda_fp16.h>
#include <cstdint>
#include <math.h>

// ----------------------------------------------------------------------------
// Problem constants
// ----------------------------------------------------------------------------
#define S_DIM   2048
#define B_DIM   16
#define H2_DIM  2048
#define V_DIM   1024
#define M_DIM   (S_DIM * B_DIM)          // 32768
#define K_TOT   (2 * H2_DIM)             // 4096
#define ALPHA_S 0.5f

// ----------------------------------------------------------------------------
// GEMM tiling: CTA 256x128, warp 64x64 (8 warps = 4x2), KT=64, 4 stages, fp16
// ----------------------------------------------------------------------------
#define MT 256
#define NTILE 128
#define KT 64
#define NCHUNK  (K_TOT / KT)             // 64
#define NTILES  (V_DIM / NTILE)          // 8
#define MTILES  (M_DIM / MT)             // 128
#define STAGES  4

// SMEM strides in HALVES. Byte row strides ≡ 16 (mod 128) -> every ldmatrix
// quadrant hits 8 distinct 16B bank groups: conflict-free.
#define A_STRIDE_H 72    // 144 B rows
#define B_STRIDE_H 136   // 272 B rows
#define C_STRIDE   136   // floats (epilogue overlay)

#define A_STAGE_HALVES (MT * A_STRIDE_H)             // 18432
#define B_STAGE_HALVES (KT * B_STRIDE_H)             // 8704
#define STAGE_HALVES   (A_STAGE_HALVES + B_STAGE_HALVES)   // 27136
#define STAGE_BYTES    (STAGE_HALVES * 2)            // 54272
#define STAGE_AREA_BYTES (STAGES * STAGE_BYTES)      // 217088
#define BIAS_OFF_B  STAGE_AREA_BYTES                 // bytes (16B aligned)
#define VW_OFF_B    (BIAS_OFF_B + NTILE * 4)
#define SMEM_BYTES  (VW_OFF_B + NTILE * 4)           // 218112 (< 227 KB cap)

// ----------------------------------------------------------------------------
// Device scratch (static — no runtime allocation)
// ----------------------------------------------------------------------------
__device__ __align__(128) __half g_A[(size_t)M_DIM * K_TOT];   // 256 MB [m][k] = rn_fp16(hidden|z)
__device__ __align__(128) __half g_B[(size_t)K_TOT * V_DIM];   // 8 MB   [k][n] = rn_fp16(Ww|Wz)
__device__ __align__(128) float  g_part[NTILES * M_DIM];       // 1 MB

// ----------------------------------------------------------------------------
// PTX helpers
// ----------------------------------------------------------------------------
__device__ __forceinline__ uint32_t smem_u32(const void* p) {
    uint32_t a;
    asm("{ .reg .u64 t; cvta.to.shared.u64 t, %1; cvt.u32.u64 %0, t; }" : "=r"(a) : "l"(p));
    return a;
}
__device__ __forceinline__ void cp_async16(uint32_t dst, const void* src) {
    asm volatile("cp.async.cg.shared.global [%0], [%1], 16;" :: "r"(dst), "l"(src) : "memory");
}
#define CP_COMMIT_GROUP()  asm volatile("cp.async.commit_group;" ::: "memory")
#define CP_WAIT_GROUP(n)   asm volatile("cp.async.wait_group %0;" :: "n"(n) : "memory")

__device__ __forceinline__ void ldsm_x4(uint32_t* r, uint32_t addr) {
    asm volatile("ldmatrix.sync.aligned.m8n8.x4.shared.b16 {%0,%1,%2,%3}, [%4];"
                 : "=r"(r[0]), "=r"(r[1]), "=r"(r[2]), "=r"(r[3]) : "r"(addr));
}
__device__ __forceinline__ void ldsm_x4_trans(uint32_t& r0, uint32_t& r1,
                                              uint32_t& r2, uint32_t& r3, uint32_t addr) {
    asm volatile("ldmatrix.sync.aligned.m8n8.x4.trans.shared.b16 {%0,%1,%2,%3}, [%4];"
                 : "=r"(r0), "=r"(r1), "=r"(r2), "=r"(r3) : "r"(addr));
}
// fp16 MMA, fp32 accumulate: D = A(16x16) * B(16x8) + D
__device__ __forceinline__ void mma_f16(float* c, const uint32_t* a, const uint32_t* b) {
    asm volatile(
        "mma.sync.aligned.m16n8k16.row.col.f32.f16.f16.f32 "
        "{%0,%1,%2,%3}, {%4,%5,%6,%7}, {%8,%9}, {%0,%1,%2,%3};"
        : "+f"(c[0]), "+f"(c[1]), "+f"(c[2]), "+f"(c[3])
        : "r"(a[0]), "r"(a[1]), "r"(a[2]), "r"(a[3]), "r"(b[0]), "r"(b[1]));
}

// ----------------------------------------------------------------------------
// Kernel 0a: pre-round A = [hidden | z] -> g_A[m][4096], RN to fp16
// ----------------------------------------------------------------------------
__global__ void __launch_bounds__(256)
preround_A(const float4* __restrict__ hidden, const float4* __restrict__ z) {
    size_t idx = (size_t)blockIdx.x * 256 + threadIdx.x;   // over M*512 groups
    size_t m = idx >> 9;
    int g = (int)(idx & 511);
    const float4* src = (g < 256) ? (hidden + m * 512 + g * 2)
                                  : (z + m * 512 + (g - 256) * 2);
    float4 v0 = src[0], v1 = src[1];
    __half2 h0 = __float22half2_rn(make_float2(v0.x, v0.y));
    __half2 h1 = __float22half2_rn(make_float2(v0.z, v0.w));
    __half2 h2 = __float22half2_rn(make_float2(v1.x, v1.y));
    __half2 h3 = __float22half2_rn(make_float2(v1.z, v1.w));
    uint4 o;
    o.x = *reinterpret_cast<uint32_t*>(&h0);
    o.y = *reinterpret_cast<uint32_t*>(&h1);
    o.z = *reinterpret_cast<uint32_t*>(&h2);
    o.w = *reinterpret_cast<uint32_t*>(&h3);
    reinterpret_cast<uint4*>(g_A)[idx] = o;
}

// ----------------------------------------------------------------------------
// Kernel 0b: pre-round B = [Ww ; Wz] -> g_B[k][1024], RN to fp16
// ----------------------------------------------------------------------------
__global__ void __launch_bounds__(256)
preround_B(const float4* __restrict__ Ww, const float4* __restrict__ Wz) {
    size_t idx = (size_t)blockIdx.x * 256 + threadIdx.x;   // over K_TOT*128 groups
    size_t k = idx >> 7;
    int g = (int)(idx & 127);
    const float4* src = (k < H2_DIM) ? (Ww + k * 256 + g * 2)
                                     : (Wz + (k - H2_DIM) * 256 + g * 2);
    float4 v0 = src[0], v1 = src[1];
    __half2 h0 = __float22half2_rn(make_float2(v0.x, v0.y));
    __half2 h1 = __float22half2_rn(make_float2(v0.z, v0.w));
    __half2 h2 = __float22half2_rn(make_float2(v1.x, v1.y));
    __half2 h3 = __float22half2_rn(make_float2(v1.z, v1.w));
    uint4 o;
    o.x = *reinterpret_cast<uint32_t*>(&h0);
    o.y = *reinterpret_cast<uint32_t*>(&h1);
    o.z = *reinterpret_cast<uint32_t*>(&h2);
    o.w = *reinterpret_cast<uint32_t*>(&h3);
    reinterpret_cast<uint4*>(g_B)[idx] = o;
}

// ----------------------------------------------------------------------------
// Stage fill: A tile [256 x 64]h, B tile [64 x 128]h; 256 threads, 8+4 cp.async
// ----------------------------------------------------------------------------
__device__ __forceinline__ void fill_stage(
    uint32_t smem_base, int slot, int kc, int mtile, int ntile, int tid)
{
    const int k0 = kc * KT;
    uint32_t aBase = smem_base + (uint32_t)(slot * STAGE_BYTES);
    uint32_t bBase = aBase + (uint32_t)(A_STAGE_HALVES * 2);

    // A: 256 rows x 8 chunks(16B = 8 halves) = 2048 chunks
    const __half* abase = g_A + k0;
#pragma unroll
    for (int i = 0; i < 8; i++) {
        int idx = tid + i * 256;
        int r = idx >> 3, g = idx & 7;
        const __half* src = abase + (size_t)(mtile * MT + r) * K_TOT + g * 8;
        uint32_t dst = aBase + (uint32_t)(r * A_STRIDE_H + g * 8) * 2u;
        cp_async16(dst, src);
    }
    // B: 64 rows x 16 chunks(16B) = 1024 chunks
    const __half* bbase = g_B + (size_t)k0 * V_DIM + ntile * NTILE;
#pragma unroll
    for (int i = 0; i < 4; i++) {
        int idx = tid + i * 256;
        int r = idx >> 4, c = idx & 15;
        const __half* src = bbase + (size_t)r * V_DIM + c * 8;
        uint32_t dst = bBase + (uint32_t)(r * B_STRIDE_H + c * 8) * 2u;
        cp_async16(dst, src);
    }
    CP_COMMIT_GROUP();
}

// ----------------------------------------------------------------------------
// Kernel 1: fused fp16 GEMM (mma.sync m16n8k16 + ldmatrix) + tanh-dot epilogue
// 4-stage ring, ONE barrier per chunk:
//   fill(kc+3) writes slot (kc+3)%4 == (kc-1)%4; every warp finished its
//   MMAs on chunk kc-1 before arriving at barrier(kc), so the write is safe.
// ----------------------------------------------------------------------------
__global__ void __launch_bounds__(256, 1)
dual_attn_gemm_kernel(const float* __restrict__ bw, const float* __restrict__ bz,
                      const float* __restrict__ Vw, const float* __restrict__ w_a)
{
    extern __shared__ char smem[];
    float* smemf = reinterpret_cast<float*>(smem);
    uint32_t smem_base = smem_u32(smem);
    const int tid  = threadIdx.x;
    const int wid  = tid >> 5;
    const int lane = tid & 31;
    const int ntile = blockIdx.x;   // 0..7 (fastest -> B resident in L2 per wave)
    const int mtile = blockIdx.y;   // 0..127

    const int warp_m = wid & 3;     // 64-row slab
    const int warp_n = wid >> 2;    // 64-col slab

    // ldmatrix quadrant mapping (q = lane/8)
    const int q = lane >> 3;
    const int lrow = lane & 7;
    const uint32_t aLaneOff =
        (uint32_t)(((warp_m * 64 + (q & 1) * 8 + lrow) * A_STRIDE_H + (q >> 1) * 8) * 2);
    const uint32_t bLaneOff =
        (uint32_t)((((q & 1) * 8 + lrow) * B_STRIDE_H + warp_n * 64 + (q >> 1) * 8) * 2);

    float* biasS = reinterpret_cast<float*>(smem + BIAS_OFF_B);
    float* vwS   = reinterpret_cast<float*>(smem + VW_OFF_B);
    {
        float wa = __ldg(w_a) * ALPHA_S;   // inside tanh: NOT shift-invariant
        if (tid < 128) {
            int n = ntile * NTILE + tid;
            biasS[tid] = bw[n] + bz[n] + wa;
            vwS[tid]   = Vw[n];
        }
    }

    float acc[4][8][4];
#pragma unroll
    for (int i = 0; i < 4; i++)
#pragma unroll
        for (int j = 0; j < 8; j++)
#pragma unroll
            for (int t = 0; t < 4; t++)
                acc[i][j][t] = 0.0f;

    // Prologue: fill stages 0..2
    fill_stage(smem_base, 0, 0, mtile, ntile, tid);
    fill_stage(smem_base, 1, 1, mtile, ntile, tid);
    fill_stage(smem_base, 2, 2, mtile, ntile, tid);

    for (int kc = 0; kc < NCHUNK; kc++) {
        // Arrival of this thread's stage-kc data (outstanding: kc..min(kc+2,63))
        if (kc <= NCHUNK - 3)      { CP_WAIT_GROUP(2); }
        else if (kc == NCHUNK - 2) { CP_WAIT_GROUP(1); }
        else                       { CP_WAIT_GROUP(0); }
        __syncthreads();   // stage kc visible to all; all warps done with kc-1

        // Refill the slot vacated by chunk kc-1
        if (kc + 3 < NCHUNK)
            fill_stage(smem_base, (kc + 3) & 3, kc + 3, mtile, ntile, tid);

        const int slot = kc & 3;
        const uint32_t aStage = smem_base + (uint32_t)(slot * STAGE_BYTES);
        const uint32_t bStage = aStage + (uint32_t)(A_STAGE_HALVES * 2);

        uint32_t a[2][4][4];
        uint32_t b[2][8][2];

        // preload ks=0 fragments
#pragma unroll
        for (int i = 0; i < 4; i++)
            ldsm_x4(a[0][i], aStage + aLaneOff + (uint32_t)(i * 16 * A_STRIDE_H * 2));
#pragma unroll
        for (int p = 0; p < 4; p++)
            ldsm_x4_trans(b[0][2 * p][0], b[0][2 * p][1],
                          b[0][2 * p + 1][0], b[0][2 * p + 1][1],
                          bStage + bLaneOff + (uint32_t)(p * 16 * 2));

#pragma unroll
        for (int ks = 0; ks < KT / 16; ks++) {
            const int cur = ks & 1;
            const int nxt = cur ^ 1;
            if (ks < KT / 16 - 1) {
                // prefetch ks+1 fragments; latency hides under the 32 MMAs below
#pragma unroll
                for (int i = 0; i < 4; i++)
                    ldsm_x4(a[nxt][i],
                            aStage + aLaneOff +
                            (uint32_t)((i * 16 * A_STRIDE_H + (ks + 1) * 16) * 2));
                uint32_t bks = bStage + bLaneOff + (uint32_t)((ks + 1) * 16 * B_STRIDE_H * 2);
#pragma unroll
                for (int p = 0; p < 4; p++)
                    ldsm_x4_trans(b[nxt][2 * p][0], b[nxt][2 * p][1],
                                  b[nxt][2 * p + 1][0], b[nxt][2 * p + 1][1],
                                  bks + (uint32_t)(p * 16 * 2));
            }
#pragma unroll
            for (int i = 0; i < 4; i++)
#pragma unroll
                for (int j = 0; j < 8; j++)
                    mma_f16(acc[i][j], a[cur][i], b[cur][j]);
        }
        // no tail barrier: 4-stage ring + top-of-loop barrier covers reuse
    }
    __syncthreads();   // all MMAs done before C overlay clobbers stage area

    // ---- Epilogue: acc -> SMEM overlay (256 x 136 fp32), tanh-dot with Vw ----
    float* Cs = smemf;   // 256*136*4 = 139264 B <= stage area (217088 B)
    {
        int gr = lane >> 2, gc = lane & 3;
#pragma unroll
        for (int i = 0; i < 4; i++) {
            int r0 = warp_m * 64 + i * 16 + gr;
#pragma unroll
            for (int j = 0; j < 8; j++) {
                int c0 = warp_n * 64 + j * 8 + 2 * gc;
                *reinterpret_cast<float2*>(Cs + r0 * C_STRIDE + c0) =
                    make_float2(acc[i][j][0], acc[i][j][1]);
                *reinterpret_cast<float2*>(Cs + (r0 + 8) * C_STRIDE + c0) =
                    make_float2(acc[i][j][2], acc[i][j][3]);
            }
        }
    }
    __syncthreads();

    // 256 threads: one row each, sum 128 columns (float4 vectorized; row
    // stride 136 floats = 544 B, 16B-aligned)
    {
        const float4* crow4 = reinterpret_cast<const float4*>(smemf + (size_t)tid * C_STRIDE);
        const float4* bb4   = reinterpret_cast<const float4*>(biasS);
        const float4* vv4   = reinterpret_cast<const float4*>(vwS);
        float acc_u = 0.0f;
#pragma unroll 8
        for (int c4 = 0; c4 < NTILE / 4; c4++) {
            float4 x4 = crow4[c4];
            float4 b4 = bb4[c4];
            float4 v4 = vv4[c4];
            float x, e, t;
            x = x4.x + b4.x; e = __expf(2.0f * x); t = 1.0f - 2.0f / (e + 1.0f); acc_u += t * v4.x;
            x = x4.y + b4.y; e = __expf(2.0f * x); t = 1.0f - 2.0f / (e + 1.0f); acc_u += t * v4.y;
            x = x4.z + b4.z; e = __expf(2.0f * x); t = 1.0f - 2.0f / (e + 1.0f); acc_u += t * v4.z;
            x = x4.w + b4.w; e = __expf(2.0f * x); t = 1.0f - 2.0f / (e + 1.0f); acc_u += t * v4.w;
        }
        g_part[(size_t)ntile * M_DIM + mtile * MT + tid] = acc_u;
    }
}

// ----------------------------------------------------------------------------
// Kernel 2: softmax over sequence dim (one block per batch column)
// ----------------------------------------------------------------------------
__global__ void __launch_bounds__(1024)
softmax_kernel(float* __restrict__ out) {
    int b = blockIdx.x;      // 0..15
    int tid = threadIdx.x;   // 0..1023
    __shared__ float red[1024];

    float u[2];
    float lmax = -1e30f;
#pragma unroll
    for (int i = 0; i < 2; i++) {
        int s = tid + i * 1024;
        size_t m = (size_t)s * B_DIM + b;
        float v = 0.0f;
#pragma unroll
        for (int t = 0; t < NTILES; t++)
            v += g_part[(size_t)t * M_DIM + m];
        u[i] = v;
        lmax = fmaxf(lmax, v);
    }
    red[tid] = lmax;
    __syncthreads();
    for (int off = 512; off > 0; off >>= 1) {
        if (tid < off) red[tid] = fmaxf(red[tid], red[tid + off]);
        __syncthreads();
    }
    float gmax = red[0];
    __syncthreads();

    float lsum = 0.0f;
#pragma unroll
    for (int i = 0; i < 2; i++) {
        u[i] = __expf(u[i] - gmax);
        lsum += u[i];
    }
    red[tid] = lsum;
    __syncthreads();
    for (int off = 512; off > 0; off >>= 1) {
        if (tid < off) red[tid] += red[tid + off];
        __syncthreads();
    }
    float inv = 1.0f / red[0];
#pragma unroll
    for (int i = 0; i < 2; i++) {
        int s = tid + i * 1024;
        out[(size_t)s * B_DIM + b] = u[i] * inv;
    }
}

// ----------------------------------------------------------------------------
// Launch
// ----------------------------------------------------------------------------
extern "C" void kernel_launch(void* const* d_in, const int* in_sizes, int n_in,
                              void* d_out, int out_size) {
    (void)in_sizes; (void)n_in; (void)out_size;
    const float* hidden = (const float*)d_in[0];
    const float* z      = (const float*)d_in[1];
    const float* Ww     = (const float*)d_in[2];
    const float* bw     = (const float*)d_in[3];
    const float* Wz     = (const float*)d_in[4];
    const float* bz     = (const float*)d_in[5];
    const float* Vw     = (const float*)d_in[6];
    // d_in[7] = vb (softmax-shift-invariant, unused)
    const float* w_a    = (const float*)d_in[8];
    float* out = (float*)d_out;

    static int smem_set = 0;
    if (!smem_set) {
        cudaFuncSetAttribute(dual_attn_gemm_kernel,
                             cudaFuncAttributeMaxDynamicSharedMemorySize, SMEM_BYTES);
        smem_set = 1;
    }

    // Pre-round inputs to fp16 (RN; 11-bit mantissa = tf32-equivalent precision)
    preround_A<<<(int)(((size_t)M_DIM * 512) / 256), 256>>>(
        (const float4*)hidden, (const float4*)z);
    preround_B<<<(int)(((size_t)K_TOT * 128) / 256), 256>>>(
        (const float4*)Ww, (const float4*)Wz);

    dual_attn_gemm_kernel<<<dim3(NTILES, MTILES), 256, SMEM_BYTES>>>(bw, bz, Vw, w_a);
    softmax_kernel<<<B_DIM, 1024>>>(out);
}